// round 14
// baseline (speedup 1.0000x reference)
#include <cuda_runtime.h>
#include <cuda_fp16.h>
#include <cstdint>

// Problem constants (fixed by setup_inputs)
#define G_SIZE   1024
#define BATCH    32
#define DDIM     256
#define ROWS     (BATCH * G_SIZE)          // 32768
#define NORM_F   0.0625f                   // 1/sqrt(256)
#define LOG2E_F  1.4426950408889634f

typedef __half f16;

// ---------------------------------------------------------------------------
// Scratch (static device globals -- no allocation allowed). All fp16 single.
// ---------------------------------------------------------------------------
__device__ f16 g_data[(size_t)ROWS * DDIM];
__device__ f16 g_dG  [(size_t)ROWS * DDIM];   // gathered kept-key data rows
__device__ f16 g_Wq[DDIM * DDIM];
__device__ f16 g_Wk[DDIM * DDIM];
__device__ f16 g_Wv[DDIM * DDIM];
__device__ f16 g_WvT[DDIM * DDIM];            // Wv transposed: [in][v]
__device__ f16 g_Wo[DDIM * DDIM];
__device__ f16 g_Wvo[DDIM * DDIM];            // Wo @ Wv : [n][in]
__device__ f16 g_Q [(size_t)ROWS * DDIM];
__device__ f16 g_K [(size_t)ROWS * DDIM];     // Kg[b][j][d]
__device__ f16 g_VWoT[(size_t)ROWS * DDIM];   // (V@Wo^T)^T : [b][n][j], ld G
__device__ f16 g_E [(size_t)BATCH * G_SIZE * G_SIZE];
__device__ float g_rowsum[ROWS];
__device__ int   g_kidx[BATCH * G_SIZE];
__device__ int   g_nk[BATCH];

// ---------------------------------------------------------------------------
// PTX helpers (sm_80-era only -- compile on plain sm_100)
// ---------------------------------------------------------------------------
__device__ __forceinline__ uint32_t smem_u32(const void* p) {
    uint32_t a;
    asm("{ .reg .u64 t; cvta.to.shared.u64 t, %1; cvt.u32.u64 %0, t; }" : "=r"(a) : "l"(p));
    return a;
}
__device__ __forceinline__ void cp16(uint32_t dst, const void* src) {
    asm volatile("cp.async.cg.shared.global [%0], [%1], 16;" :: "r"(dst), "l"(src));
}
#define CP_COMMIT() asm volatile("cp.async.commit_group;" ::: "memory")
#define CP_WAIT1()  asm volatile("cp.async.wait_group 1;" ::: "memory")

#define LDSM4(r0, r1, r2, r3, addr) \
    asm volatile("ldmatrix.sync.aligned.m8n8.x4.shared.b16 {%0,%1,%2,%3}, [%4];" \
                 : "=r"(r0), "=r"(r1), "=r"(r2), "=r"(r3) : "r"(addr))

#define MMA_F16(c, a, b) \
    asm volatile("mma.sync.aligned.m16n8k16.row.col.f32.f16.f16.f32 " \
                 "{%0,%1,%2,%3},{%4,%5,%6,%7},{%8,%9},{%0,%1,%2,%3};" \
                 : "+f"((c)[0]), "+f"((c)[1]), "+f"((c)[2]), "+f"((c)[3]) \
                 : "r"((a)[0]), "r"((a)[1]), "r"((a)[2]), "r"((a)[3]), \
                   "r"((b)[0]), "r"((b)[1]))

// packed 2^x on fp16 pair (MUFU, 2 elements per op)
__device__ __forceinline__ __half2 ex2_h2(__half2 t) {
    uint32_t r, s = *(uint32_t*)&t;
    asm("ex2.approx.f16x2 %0, %1;" : "=r"(r) : "r"(s));
    return *(__half2*)&r;
}

// ---------------------------------------------------------------------------
// Shared GEMM config
// ---------------------------------------------------------------------------
#define STAGES 3
#define TILE_BYTES 16384
#define STAGE_BYTES (2 * TILE_BYTES)        // A, B
#define SMEM_DYN (STAGES * STAGE_BYTES)     // 98304

struct GemmArgs {
    const f16 *A, *B;
    f16 *C;
    float* Cf;
    float* rowsum;
    const int* nkArr;
    int ldA, ldB, ldC;
    size_t sA, sB, sC;
    int nChunks;
    float alpha;
    const float* bias;
};

__device__ __forceinline__ void load_stage(
    uint32_t sbase, int tid,
    const f16* pA, int ldA, const f16* pB, int ldB, int kb)
{
    #pragma unroll
    for (int q = 0; q < 4; q++) {
        const int idx = tid + q * 256;
        const int r = idx >> 3;
        const int c = idx & 7;
        const uint32_t dst = sbase + r * 128 + ((c ^ (r & 7)) << 4);
        cp16(dst,              pA + (size_t)r * ldA + kb + c * 8);
        cp16(dst + TILE_BYTES, pB + (size_t)r * ldB + kb + c * 8);
    }
}

// ---------------------------------------------------------------------------
// Fused projection kernel: Q, Kg, VWoT in ONE continuous cp.async pipeline.
// grid (2, 8, 32). 12 virtual chunks (4 per sub-GEMM); epilogue at each
// 4-chunk boundary (register-only stores), acc reset, pipeline keeps flowing.
// CTAs with by*128 >= nk[b] run only the Q segment (4 chunks).
// ---------------------------------------------------------------------------
struct ProjArgs {
    const f16 *data, *dG, *Wq, *Wk, *Wvo;
    f16 *Q, *K, *VWoT;
    const int* nkArr;
};

__global__ void __launch_bounds__(256, 2)
gemm_proj(ProjArgs args)
{
    extern __shared__ char smem[];
    const uint32_t sbase = smem_u32(smem);

    const int tid = threadIdx.x;
    const int lane = tid & 31;
    const int wid = tid >> 5;
    const int wm = wid >> 2;
    const int wn = wid & 3;
    const int bx = blockIdx.x, by = blockIdx.y, bz = blockIdx.z;

    const int nkv = args.nkArr[bz];
    const bool doKV = (by * 128 < nkv);
    const int nv = doKV ? 12 : 4;

    const f16* aP[3];
    const f16* bP[3];
    aP[0] = args.data + (size_t)bz * G_SIZE * DDIM + (size_t)(by * 128) * DDIM;
    aP[1] = args.dG   + (size_t)bz * G_SIZE * DDIM + (size_t)(by * 128) * DDIM;
    aP[2] = aP[1];
    bP[0] = args.Wq  + (size_t)(bx * 128) * DDIM;
    bP[1] = args.Wk  + (size_t)(bx * 128) * DDIM;
    bP[2] = args.Wvo + (size_t)(bx * 128) * DDIM;

    float acc[4][4][4];
    #pragma unroll
    for (int a = 0; a < 4; a++)
        #pragma unroll
        for (int b = 0; b < 4; b++)
            #pragma unroll
            for (int c = 0; c < 4; c++) acc[a][b][c] = 0.f;

    const int i8 = lane & 7;
    const int j  = lane >> 3;
    const int mLane = wm * 64 + i8 + ((j & 1) << 3);
    const int nLane = wn * 32 + i8 + ((j >> 1) << 3);
    const int jA = j >> 1;
    const int jB = j & 1;
    const int swz = i8;
    const int lr = lane >> 2;
    const int lc = (lane & 3) * 2;
    const int nW = bx * 128 + wn * 32;

    load_stage(sbase, tid, aP[0], DDIM, bP[0], DDIM, 0);
    CP_COMMIT();
    load_stage(sbase + STAGE_BYTES, tid, aP[0], DDIM, bP[0], DDIM, 64);
    CP_COMMIT();

    for (int c = 0; c < nv; c++) {
        CP_WAIT1();
        __syncthreads();

        const int pre = c + 2;
        if (pre < nv) {
            const int pw = pre >> 2;
            load_stage(sbase + (pre % STAGES) * STAGE_BYTES, tid,
                       aP[pw], DDIM, bP[pw], DDIM, (pre & 3) * 64);
        }
        CP_COMMIT();

        const uint32_t stage = sbase + (c % STAGES) * STAGE_BYTES;
        const uint32_t aRow = stage + mLane * 128;
        const uint32_t bRow = stage + TILE_BYTES + nLane * 128;

        #pragma unroll
        for (int ks = 0; ks < 4; ks++) {
            const uint32_t aOff = aRow + (((ks * 2 + jA) ^ swz) << 4);
            const uint32_t bOff = bRow + (((ks * 2 + jB) ^ swz) << 4);

            uint32_t aF[4][4], bF[4][2];
            #pragma unroll
            for (int mt = 0; mt < 4; mt++)
                LDSM4(aF[mt][0], aF[mt][1], aF[mt][2], aF[mt][3], aOff + mt * 2048);
            #pragma unroll
            for (int np = 0; np < 2; np++) {
                uint32_t r0, r1, r2, r3;
                LDSM4(r0, r1, r2, r3, bOff + np * 2048);
                bF[np * 2][0] = r0; bF[np * 2][1] = r1;
                bF[np * 2 + 1][0] = r2; bF[np * 2 + 1][1] = r3;
            }
            #pragma unroll
            for (int mt = 0; mt < 4; mt++)
                #pragma unroll
                for (int nt = 0; nt < 4; nt++)
                    MMA_F16(acc[mt][nt], aF[mt], bF[nt]);
        }

        // Segment boundary: register-only epilogue + acc reset
        if ((c & 3) == 3) {
            const int which = c >> 2;
            if (which != 2) {
                f16* Cb = (which == 0 ? args.Q : args.K) + (size_t)bz * G_SIZE * DDIM;
                #pragma unroll
                for (int mt = 0; mt < 4; mt++) {
                    const int m = by * 128 + wm * 64 + mt * 16 + lr;
                    #pragma unroll
                    for (int nt = 0; nt < 4; nt++) {
                        const int n = nW + nt * 8 + lc;
                        const float* a = acc[mt][nt];
                        *(__half2*)(Cb + (size_t)m * DDIM + n) =
                            __floats2half2_rn(a[0], a[1]);
                        *(__half2*)(Cb + (size_t)(m + 8) * DDIM + n) =
                            __floats2half2_rn(a[2], a[3]);
                    }
                }
            } else {
                f16* Cb = args.VWoT + (size_t)bz * DDIM * G_SIZE;
                #pragma unroll
                for (int mt = 0; mt < 4; mt++) {
                    const int m = by * 128 + wm * 64 + mt * 16 + lr;
                    #pragma unroll
                    for (int nt = 0; nt < 4; nt++) {
                        const int n = nW + nt * 8 + lc;
                        const float* a = acc[mt][nt];
                        Cb[(size_t)n * G_SIZE + m]           = __float2half_rn(a[0]);
                        Cb[(size_t)(n + 1) * G_SIZE + m]     = __float2half_rn(a[1]);
                        Cb[(size_t)n * G_SIZE + m + 8]       = __float2half_rn(a[2]);
                        Cb[(size_t)(n + 1) * G_SIZE + m + 8] = __float2half_rn(a[3]);
                    }
                }
            }
            #pragma unroll
            for (int a = 0; a < 4; a++)
                #pragma unroll
                for (int b = 0; b < 4; b++)
                    #pragma unroll
                    for (int cc = 0; cc < 4; cc++) acc[a][b][cc] = 0.f;
        }
    }
}

// ---------------------------------------------------------------------------
// Generic fp16 NT GEMM (MODES 1, 3, 6) -- unchanged proven core
// MODE 1: C fp16 normal store (Wvo precompute)
// MODE 3: E = 2^(alpha*acc) masked, + rowsum
// MODE 6: Cf fp32 = acc / rowsum + bias; K chunks = ceil(nk/64)
// ---------------------------------------------------------------------------
template <int MODE>
__global__ void __launch_bounds__(256, 2)
gemm_mma(GemmArgs args)
{
    extern __shared__ char smem[];
    const uint32_t sbase = smem_u32(smem);

    const int tid = threadIdx.x;
    const int lane = tid & 31;
    const int wid = tid >> 5;
    const int wm = wid >> 2;
    const int wn = wid & 3;
    const int bx = blockIdx.x, by = blockIdx.y, bz = blockIdx.z;

    int nkv = 0;
    if (MODE == 3) {
        nkv = args.nkArr[bz];
        if (bx * 128 >= nkv) return;
    }
    int nChunks = args.nChunks;
    if (MODE == 6) nChunks = (args.nkArr[bz] + 63) >> 6;

    const int ldA = args.ldA, ldB = args.ldB;
    const f16* pA = args.A + (size_t)bz * args.sA + (size_t)(by * 128) * ldA;
    const f16* pB = args.B + (size_t)bz * args.sB + (size_t)(bx * 128) * ldB;

    float acc[4][4][4];
    #pragma unroll
    for (int a = 0; a < 4; a++)
        #pragma unroll
        for (int b = 0; b < 4; b++)
            #pragma unroll
            for (int c = 0; c < 4; c++) acc[a][b][c] = 0.f;

    const int i8 = lane & 7;
    const int j  = lane >> 3;
    const int mLane = wm * 64 + i8 + ((j & 1) << 3);
    const int nLane = wn * 32 + i8 + ((j >> 1) << 3);
    const int jA = j >> 1;
    const int jB = j & 1;
    const int swz = i8;

    load_stage(sbase, tid, pA, ldA, pB, ldB, 0);
    CP_COMMIT();
    load_stage(sbase + STAGE_BYTES, tid, pA, ldA, pB, ldB, 64);
    CP_COMMIT();

    for (int ch = 0; ch < nChunks; ch++) {
        CP_WAIT1();
        __syncthreads();

        const int pre = ch + 2;
        if (pre < nChunks) {
            load_stage(sbase + (pre % STAGES) * STAGE_BYTES, tid,
                       pA, ldA, pB, ldB, pre * 64);
        }
        CP_COMMIT();

        const uint32_t stage = sbase + (ch % STAGES) * STAGE_BYTES;
        const uint32_t aRow = stage + mLane * 128;
        const uint32_t bRow = stage + TILE_BYTES + nLane * 128;

        #pragma unroll
        for (int ks = 0; ks < 4; ks++) {
            const uint32_t aOff = aRow + (((ks * 2 + jA) ^ swz) << 4);
            const uint32_t bOff = bRow + (((ks * 2 + jB) ^ swz) << 4);

            uint32_t aF[4][4], bF[4][2];
            #pragma unroll
            for (int mt = 0; mt < 4; mt++)
                LDSM4(aF[mt][0], aF[mt][1], aF[mt][2], aF[mt][3], aOff + mt * 2048);
            #pragma unroll
            for (int np = 0; np < 2; np++) {
                uint32_t r0, r1, r2, r3;
                LDSM4(r0, r1, r2, r3, bOff + np * 2048);
                bF[np * 2][0] = r0; bF[np * 2][1] = r1;
                bF[np * 2 + 1][0] = r2; bF[np * 2 + 1][1] = r3;
            }
            #pragma unroll
            for (int mt = 0; mt < 4; mt++)
                #pragma unroll
                for (int nt = 0; nt < 4; nt++)
                    MMA_F16(acc[mt][nt], aF[mt], bF[nt]);
        }
    }

    // Epilogue
    const int nW = bx * 128 + wn * 32;
    const int lr = lane >> 2;
    const int lc = (lane & 3) * 2;
    const float alpha = args.alpha;

    f16* Cbase = (MODE != 6) ? (args.C + (size_t)bz * args.sC) : nullptr;

    float* rsmem = (float*)smem;
    if (MODE == 3) {
        __syncthreads();
        if (tid < 128) rsmem[tid] = 0.f;
        __syncthreads();
    }

    float bA[4], bB[4];
    int mkA[4], mkB[4];
    #pragma unroll
    for (int nt = 0; nt < 4; nt++) {
        const int n = nW + nt * 8 + lc;
        if (MODE == 6) { bA[nt] = args.bias[n]; bB[nt] = args.bias[n + 1]; }
        if (MODE == 3) { mkA[nt] = (n >= nkv); mkB[nt] = (n + 1 >= nkv); }
    }

    #pragma unroll
    for (int mt = 0; mt < 4; mt++) {
        const int mloc = wm * 64 + mt * 16 + lr;
        const int m = by * 128 + mloc;
        float inv0 = 1.f, inv8 = 1.f;
        if (MODE == 6) {
            const float* rs = args.rowsum + (size_t)bz * G_SIZE + by * 128;
            inv0 = 1.f / rs[mloc];
            inv8 = 1.f / rs[mloc + 8];
        }
        float p0 = 0.f, p8 = 0.f;

        #pragma unroll
        for (int nt = 0; nt < 4; nt++) {
            const int n = nW + nt * 8 + lc;
            const float* a = acc[mt][nt];

            if (MODE == 6) {
                float v0 = a[0] * inv0 + bA[nt], v1 = a[1] * inv0 + bB[nt];
                float v2 = a[2] * inv8 + bA[nt], v3 = a[3] * inv8 + bB[nt];
                float* base = args.Cf + (size_t)bz * args.sC;
                *(float2*)(base + (size_t)m * args.ldC + n)       = make_float2(v0, v1);
                *(float2*)(base + (size_t)(m + 8) * args.ldC + n) = make_float2(v2, v3);
                continue;
            }
            if (MODE == 3) {
                float x0 = mkA[nt] ? -1e4f : a[0] * alpha;
                float x1 = mkB[nt] ? -1e4f : a[1] * alpha;
                float x2 = mkA[nt] ? -1e4f : a[2] * alpha;
                float x3 = mkB[nt] ? -1e4f : a[3] * alpha;
                __half2 eA = ex2_h2(__floats2half2_rn(x0, x1));
                __half2 eB = ex2_h2(__floats2half2_rn(x2, x3));
                float2 fA = __half22float2(eA);
                float2 fB = __half22float2(eB);
                p0 += fA.x + fA.y;
                p8 += fB.x + fB.y;
                *(__half2*)(Cbase + (size_t)m * args.ldC + n)       = eA;
                *(__half2*)(Cbase + (size_t)(m + 8) * args.ldC + n) = eB;
                continue;
            }
            // MODE 1
            *(__half2*)(Cbase + (size_t)m * args.ldC + n) =
                __floats2half2_rn(a[0], a[1]);
            *(__half2*)(Cbase + (size_t)(m + 8) * args.ldC + n) =
                __floats2half2_rn(a[2], a[3]);
        }

        if (MODE == 3) {
            p0 += __shfl_xor_sync(0xffffffffu, p0, 1);
            p0 += __shfl_xor_sync(0xffffffffu, p0, 2);
            p8 += __shfl_xor_sync(0xffffffffu, p8, 1);
            p8 += __shfl_xor_sync(0xffffffffu, p8, 2);
            if ((lane & 3) == 0) {
                atomicAdd(&rsmem[mloc], p0);
                atomicAdd(&rsmem[mloc + 8], p8);
            }
        }
    }

    if (MODE == 3) {
        __syncthreads();
        if (tid < 128)
            atomicAdd(args.rowsum + (size_t)bz * G_SIZE + by * 128 + tid, rsmem[tid]);
    }
}

// ---------------------------------------------------------------------------
// Fused fp32 -> fp16 convert: data + 4 weights; also emits WvT (transposed Wv)
// ---------------------------------------------------------------------------
#define N_DATA4 (ROWS * DDIM / 4)
#define N_W4    (DDIM * DDIM / 4)
#define N_CVT4  (N_DATA4 + 4 * N_W4)

__global__ void __launch_bounds__(256)
cvt_all_kernel(const float4* __restrict__ data,
               const float4* __restrict__ wq, const float4* __restrict__ wk,
               const float4* __restrict__ wv, const float4* __restrict__ wo,
               f16* __restrict__ dataF,
               f16* __restrict__ wqF, f16* __restrict__ wkF,
               f16* __restrict__ wvF, f16* __restrict__ wvT,
               f16* __restrict__ woF)
{
    const int i = blockIdx.x * 256 + threadIdx.x;
    if (i >= N_CVT4) return;
    const float4* src;
    f16* dst;
    int off;
    int w = -1;
    if (i < N_DATA4) { src = data; dst = dataF; off = i; }
    else {
        const int jj = i - N_DATA4;
        w = jj / N_W4;
        off = jj - w * N_W4;
        src = (w == 0) ? wq : (w == 1) ? wk : (w == 2) ? wv : wo;
        dst = (w == 0) ? wqF : (w == 1) ? wkF : (w == 2) ? wvF : woF;
    }
    const float4 v = src[off];
    f16 h0 = __float2half_rn(v.x), h1 = __float2half_rn(v.y);
    f16 h2 = __float2half_rn(v.z), h3 = __float2half_rn(v.w);
    ((__half2*)dst)[off * 2]     = {h0, h1};
    ((__half2*)dst)[off * 2 + 1] = {h2, h3};
    if (w == 2) {
        const int row = (off * 4) >> 8;
        const int col = (off * 4) & 255;
        wvT[(col + 0) * DDIM + row] = h0;
        wvT[(col + 1) * DDIM + row] = h1;
        wvT[(col + 2) * DDIM + row] = h2;
        wvT[(col + 3) * DDIM + row] = h3;
    }
}

// ---------------------------------------------------------------------------
// Fused: mask compaction + rowsum zero + key-row gather. One block per batch.
// ---------------------------------------------------------------------------
__global__ void __launch_bounds__(1024)
compact_gather_kernel(const int* __restrict__ mask, const f16* __restrict__ dataF,
                      int* __restrict__ kidx, int* __restrict__ nk,
                      float* __restrict__ rowsum, f16* __restrict__ dG)
{
    const int b = blockIdx.x;
    const int g = threadIdx.x;

    rowsum[b * G_SIZE + g] = 0.f;

    const int keep = (mask[b * G_SIZE + g] == 0);
    __shared__ int warpCnt[32];
    __shared__ int s_nk;
    const uint32_t bal = __ballot_sync(0xffffffffu, keep);
    const int lane = g & 31, w = g >> 5;
    const int pre = __popc(bal & ((1u << lane) - 1));
    if (lane == 0) warpCnt[w] = __popc(bal);
    __syncthreads();
    int base = 0;
    for (int i = 0; i < w; i++) base += warpCnt[i];
    if (keep) kidx[b * G_SIZE + base + pre] = g;
    if (g == 0) {
        int t = 0;
        for (int i = 0; i < 32; i++) t += warpCnt[i];
        nk[b] = t;
        s_nk = t;
    }
    __syncthreads();

    const int n = s_nk;
    const int npad = (n + 127) & ~127;
    const int total = npad * 32;
    for (int idx = g; idx < total; idx += 1024) {
        const int jr = idx >> 5;
        const int c = idx & 31;
        uint4 v = make_uint4(0, 0, 0, 0);
        if (jr < n) {
            const size_t src = (size_t)(b * G_SIZE + kidx[b * G_SIZE + jr]) * DDIM;
            v = ((const uint4*)(dataF + src))[c];
        }
        ((uint4*)(dG + (size_t)(b * G_SIZE + jr) * DDIM))[c] = v;
    }
}

// ---------------------------------------------------------------------------
// Launch (6 kernels total)
// ---------------------------------------------------------------------------
extern "C" void kernel_launch(void* const* d_in, const int* in_sizes, int n_in,
                              void* d_out, int out_size)
{
    const float* data = (const float*)d_in[0];
    const int*   mask = (const int*)  d_in[1];
    const float* Wq   = (const float*)d_in[4];
    const float* Wk   = (const float*)d_in[5];
    const float* Wv   = (const float*)d_in[6];
    const float* Wo   = (const float*)d_in[7];
    const float* bo   = (const float*)d_in[8];
    float*       out  = (float*)d_out;

    f16 *dataF, *dG, *WqF, *WkF, *WvF, *WvT, *WoF, *Wvo, *Q, *K, *VWoT, *E;
    float* rowsum;
    int *kidx, *nk;
    cudaGetSymbolAddress((void**)&dataF, g_data);
    cudaGetSymbolAddress((void**)&dG, g_dG);
    cudaGetSymbolAddress((void**)&WqF, g_Wq);
    cudaGetSymbolAddress((void**)&WkF, g_Wk);
    cudaGetSymbolAddress((void**)&WvF, g_Wv);
    cudaGetSymbolAddress((void**)&WvT, g_WvT);
    cudaGetSymbolAddress((void**)&WoF, g_Wo);
    cudaGetSymbolAddress((void**)&Wvo, g_Wvo);
    cudaGetSymbolAddress((void**)&Q, g_Q);
    cudaGetSymbolAddress((void**)&K, g_K);
    cudaGetSymbolAddress((void**)&VWoT, g_VWoT);
    cudaGetSymbolAddress((void**)&E, g_E);
    cudaGetSymbolAddress((void**)&rowsum, g_rowsum);
    cudaGetSymbolAddress((void**)&kidx, g_kidx);
    cudaGetSymbolAddress((void**)&nk, g_nk);

    cudaFuncSetAttribute(gemm_mma<1>, cudaFuncAttributeMaxDynamicSharedMemorySize, SMEM_DYN);
    cudaFuncSetAttribute(gemm_mma<3>, cudaFuncAttributeMaxDynamicSharedMemorySize, SMEM_DYN);
    cudaFuncSetAttribute(gemm_mma<6>, cudaFuncAttributeMaxDynamicSharedMemorySize, SMEM_DYN);
    cudaFuncSetAttribute(gemm_proj,   cudaFuncAttributeMaxDynamicSharedMemorySize, SMEM_DYN);

    // 1) All fp32->fp16 conversions (+ WvT transpose)
    cvt_all_kernel<<<(N_CVT4 + 255) / 256, 256>>>(
        (const float4*)data, (const float4*)Wq, (const float4*)Wk,
        (const float4*)Wv, (const float4*)Wo,
        dataF, WqF, WkF, WvF, WvT, WoF);

    // 2) Wvo[n][in] = sum_v Wo[n][v] * Wv[v][in]  (NT: A=Wo, B=WvT)
    {
        GemmArgs a = {};
        a.A = WoF; a.B = WvT; a.C = Wvo;
        a.ldA = DDIM; a.ldB = DDIM; a.ldC = DDIM;
        a.sA = 0; a.sB = 0; a.sC = 0;
        a.nChunks = DDIM / 64;
        a.alpha = 1.f;
        dim3 grd(DDIM / 128, DDIM / 128, 1);
        gemm_mma<1><<<grd, 256, SMEM_DYN>>>(a);
    }

    // 3) Compaction + rowsum zero + gather
    compact_gather_kernel<<<BATCH, 1024>>>(mask, dataF, kidx, nk, rowsum, dG);

    // 4) Fused projections (single continuous pipeline per CTA)
    {
        ProjArgs p;
        p.data = dataF; p.dG = dG; p.Wq = WqF; p.Wk = WkF; p.Wvo = Wvo;
        p.Q = Q; p.K = K; p.VWoT = VWoT;
        p.nkArr = nk;
        dim3 grd(DDIM / 128, G_SIZE / 128, BATCH);
        gemm_proj<<<grd, 256, SMEM_DYN>>>(p);
    }

    // 5) E[b][q][j] = 2^(NORM*log2e * Q_b @ Kg_b^T), j >= nk -> 0, + rowsum
    {
        GemmArgs a = {};
        a.A = Q; a.B = K; a.nkArr = nk; a.rowsum = rowsum;
        a.ldA = DDIM; a.ldB = DDIM; a.ldC = G_SIZE;
        a.sA = (size_t)G_SIZE * DDIM; a.sB = (size_t)G_SIZE * DDIM;
        a.sC = (size_t)G_SIZE * G_SIZE;
        a.nChunks = DDIM / 64;
        a.alpha = NORM_F * LOG2E_F;
        a.C = E;
        dim3 grd(G_SIZE / 128, G_SIZE / 128, BATCH);
        gemm_mma<3><<<grd, 256, SMEM_DYN>>>(a);
    }

    // 6) out = (E_b @ VWoT_b^T) / rowsum + b_out   (fp32, K = ceil64(nk))
    {
        GemmArgs a = {};
        a.A = E; a.B = VWoT; a.nkArr = nk; a.rowsum = rowsum;
        a.ldA = G_SIZE; a.ldB = G_SIZE; a.ldC = DDIM;
        a.sA = (size_t)G_SIZE * G_SIZE; a.sB = (size_t)DDIM * G_SIZE;
        a.sC = (size_t)G_SIZE * DDIM;
        a.nChunks = G_SIZE / 64;
        a.alpha = 1.f;
        a.Cf = out; a.bias = bo;
        dim3 grd(DDIM / 128, G_SIZE / 128, BATCH);
        gemm_mma<6><<<grd, 256, SMEM_DYN>>>(a);
    }
}

// round 15
// speedup vs baseline: 1.0836x; 1.0836x over previous
#include <cuda_runtime.h>
#include <cuda_fp16.h>
#include <cstdint>

// Problem constants (fixed by setup_inputs)
#define G_SIZE   1024
#define BATCH    32
#define DDIM     256
#define ROWS     (BATCH * G_SIZE)          // 32768
#define NORM_F   0.0625f                   // 1/sqrt(256)
#define LOG2E_F  1.4426950408889634f

typedef __half f16;

// ---------------------------------------------------------------------------
// Scratch (static device globals -- no allocation allowed). All fp16 single.
// ---------------------------------------------------------------------------
__device__ f16 g_data[(size_t)ROWS * DDIM];
__device__ f16 g_dG  [(size_t)ROWS * DDIM];   // gathered kept-key data rows
__device__ f16 g_Wq[DDIM * DDIM];
__device__ f16 g_Wk[DDIM * DDIM];
__device__ f16 g_Wv[DDIM * DDIM];
__device__ f16 g_WvT[DDIM * DDIM];            // Wv transposed: [in][v]
__device__ f16 g_Wo[DDIM * DDIM];
__device__ f16 g_Wvo[DDIM * DDIM];            // Wo @ Wv : [n][in]
__device__ f16 g_Q [(size_t)ROWS * DDIM];
__device__ f16 g_K [(size_t)ROWS * DDIM];     // Kg[b][j][d]
__device__ f16 g_VWoT[(size_t)ROWS * DDIM];   // (V@Wo^T)^T : [b][n][j], ld G
__device__ f16 g_E [(size_t)BATCH * G_SIZE * G_SIZE];
__device__ float g_rowsum[ROWS];
__device__ int   g_kidx[BATCH * G_SIZE];
__device__ int   g_nk[BATCH];

// ---------------------------------------------------------------------------
// PTX helpers (sm_80-era only -- compile on plain sm_100)
// ---------------------------------------------------------------------------
__device__ __forceinline__ uint32_t smem_u32(const void* p) {
    uint32_t a;
    asm("{ .reg .u64 t; cvta.to.shared.u64 t, %1; cvt.u32.u64 %0, t; }" : "=r"(a) : "l"(p));
    return a;
}
__device__ __forceinline__ void cp16(uint32_t dst, const void* src) {
    asm volatile("cp.async.cg.shared.global [%0], [%1], 16;" :: "r"(dst), "l"(src));
}
#define CP_COMMIT() asm volatile("cp.async.commit_group;" ::: "memory")
#define CP_WAIT1()  asm volatile("cp.async.wait_group 1;" ::: "memory")

#define LDSM4(r0, r1, r2, r3, addr) \
    asm volatile("ldmatrix.sync.aligned.m8n8.x4.shared.b16 {%0,%1,%2,%3}, [%4];" \
                 : "=r"(r0), "=r"(r1), "=r"(r2), "=r"(r3) : "r"(addr))

#define MMA_F16(c, a, b) \
    asm volatile("mma.sync.aligned.m16n8k16.row.col.f32.f16.f16.f32 " \
                 "{%0,%1,%2,%3},{%4,%5,%6,%7},{%8,%9},{%0,%1,%2,%3};" \
                 : "+f"((c)[0]), "+f"((c)[1]), "+f"((c)[2]), "+f"((c)[3]) \
                 : "r"((a)[0]), "r"((a)[1]), "r"((a)[2]), "r"((a)[3]), \
                   "r"((b)[0]), "r"((b)[1]))

// packed 2^x on fp16 pair (MUFU, 2 elements per op)
__device__ __forceinline__ __half2 ex2_h2(__half2 t) {
    uint32_t r, s = *(uint32_t*)&t;
    asm("ex2.approx.f16x2 %0, %1;" : "=r"(r) : "r"(s));
    return *(__half2*)&r;
}

// ---------------------------------------------------------------------------
// fp16 NT GEMM:  C = alpha * A @ B^T, fp32 accumulate
// MODE 1: C fp16, plain normal-layout store (used for Wvo = Wo @ WvT^T)
// MODE 3: e = (n < nk[bz]) ? 2^(alpha*acc) : 0  (alpha includes log2e);
//         C = fp16(e) via ex2.approx.f16x2; rowsum[bz*G+m] += row sums
//         via direct global atomics; N-tiles beyond nk exit
// MODE 5: fused projections; blockIdx.z = which*32 + batch:
//         which 0: Q = data_b @ Wq^T (full rows)
//         which 1: Kg_b = dG_b @ Wk^T (M limit nk[b])
//         which 2: VWoT_b = (dG_b @ Wvo^T)^T (M limit nk[b], transposed store)
// MODE 6: Cf fp32 = acc / rowsum[bz*G+m] + bias[n]; K chunks = ceil(nk/64)
// Tile 128x128, BK=64 (128B swizzled rows), 3-stage cp.async, 1 sync/chunk.
// ---------------------------------------------------------------------------
#define STAGES 3
#define TILE_BYTES 16384
#define STAGE_BYTES (2 * TILE_BYTES)        // A, B
#define SMEM_DYN (STAGES * STAGE_BYTES)     // 98304

struct GemmArgs {
    const f16 *A, *B;
    const f16 *A2, *B2, *B3;     // MODE 5 extras
    f16 *C, *C2, *C3;
    float* Cf;
    float* rowsum;
    const int* nkArr;
    int ldA, ldB, ldC;
    size_t sA, sB, sC;
    int nChunks;
    float alpha;
    const float* bias;
};

__device__ __forceinline__ void load_stage(
    uint32_t sbase, int tid,
    const f16* pA, int ldA, const f16* pB, int ldB, int kb)
{
    #pragma unroll
    for (int q = 0; q < 4; q++) {
        const int idx = tid + q * 256;
        const int r = idx >> 3;
        const int c = idx & 7;
        const uint32_t dst = sbase + r * 128 + ((c ^ (r & 7)) << 4);
        cp16(dst,              pA + (size_t)r * ldA + kb + c * 8);
        cp16(dst + TILE_BYTES, pB + (size_t)r * ldB + kb + c * 8);
    }
}

template <int MODE>
__global__ void __launch_bounds__(256, 2)
gemm_mma(GemmArgs args)
{
    extern __shared__ char smem[];
    const uint32_t sbase = smem_u32(smem);

    const int tid = threadIdx.x;
    const int lane = tid & 31;
    const int wid = tid >> 5;
    const int wm = wid >> 2;
    const int wn = wid & 3;
    const int bx = blockIdx.x, by = blockIdx.y;

    int bz = blockIdx.z;
    int which = 0;
    if (MODE == 5) { which = bz >> 5; bz &= 31; }

    int nkv = 0;
    if (MODE == 5 && which != 0) {
        nkv = args.nkArr[bz];
        if (by * 128 >= nkv) return;
    }
    if (MODE == 3) {
        nkv = args.nkArr[bz];
        if (bx * 128 >= nkv) return;
    }
    int nChunks = args.nChunks;
    if (MODE == 6) nChunks = (args.nkArr[bz] + 63) >> 6;
    if (MODE == 5) nChunks = DDIM / 64;

    // Operand selection
    const f16 *Abase, *Bbase;
    int ldA, ldB;
    if (MODE == 5) {
        ldA = DDIM; ldB = DDIM;
        if (which == 0)      { Abase = args.A  + (size_t)bz * G_SIZE * DDIM; Bbase = args.B;  }
        else if (which == 1) { Abase = args.A2 + (size_t)bz * G_SIZE * DDIM; Bbase = args.B2; }
        else                 { Abase = args.A2 + (size_t)bz * G_SIZE * DDIM; Bbase = args.B3; }
    } else {
        ldA = args.ldA; ldB = args.ldB;
        Abase = args.A + (size_t)bz * args.sA;
        Bbase = args.B + (size_t)bz * args.sB;
    }
    const f16* pA = Abase + (size_t)(by * 128) * ldA;
    const f16* pB = Bbase + (size_t)(bx * 128) * ldB;

    float acc[4][4][4];
    #pragma unroll
    for (int a = 0; a < 4; a++)
        #pragma unroll
        for (int b = 0; b < 4; b++)
            #pragma unroll
            for (int c = 0; c < 4; c++) acc[a][b][c] = 0.f;

    const int i8 = lane & 7;
    const int j  = lane >> 3;
    const int mLane = wm * 64 + i8 + ((j & 1) << 3);
    const int nLane = wn * 32 + i8 + ((j >> 1) << 3);
    const int jA = j >> 1;
    const int jB = j & 1;
    const int swz = i8;

    load_stage(sbase, tid, pA, ldA, pB, ldB, 0);
    CP_COMMIT();
    load_stage(sbase + STAGE_BYTES, tid, pA, ldA, pB, ldB, 64);
    CP_COMMIT();

    for (int ch = 0; ch < nChunks; ch++) {
        CP_WAIT1();
        __syncthreads();    // single barrier per chunk: proves all warps done
                            // reading stage (ch-1)%3 == write target (ch+2)%3

        const int pre = ch + 2;
        if (pre < nChunks) {
            load_stage(sbase + (pre % STAGES) * STAGE_BYTES, tid,
                       pA, ldA, pB, ldB, pre * 64);
        }
        CP_COMMIT();

        const uint32_t stage = sbase + (ch % STAGES) * STAGE_BYTES;
        const uint32_t aRow = stage + mLane * 128;
        const uint32_t bRow = stage + TILE_BYTES + nLane * 128;

        #pragma unroll
        for (int ks = 0; ks < 4; ks++) {
            const uint32_t aOff = aRow + (((ks * 2 + jA) ^ swz) << 4);
            const uint32_t bOff = bRow + (((ks * 2 + jB) ^ swz) << 4);

            uint32_t aF[4][4], bF[4][2];
            #pragma unroll
            for (int mt = 0; mt < 4; mt++)
                LDSM4(aF[mt][0], aF[mt][1], aF[mt][2], aF[mt][3], aOff + mt * 2048);
            #pragma unroll
            for (int np = 0; np < 2; np++) {
                uint32_t r0, r1, r2, r3;
                LDSM4(r0, r1, r2, r3, bOff + np * 2048);
                bF[np * 2][0] = r0; bF[np * 2][1] = r1;
                bF[np * 2 + 1][0] = r2; bF[np * 2 + 1][1] = r3;
            }
            #pragma unroll
            for (int mt = 0; mt < 4; mt++)
                #pragma unroll
                for (int nt = 0; nt < 4; nt++)
                    MMA_F16(acc[mt][nt], aF[mt], bF[nt]);
        }
    }

    // ------------------------- Epilogue -------------------------
    const int nW = bx * 128 + wn * 32;
    const int lr = lane >> 2;
    const int lc = (lane & 3) * 2;
    const float alpha = args.alpha;

    // Output selection
    f16* Cbase = nullptr;
    int ldC = args.ldC;
    bool trans = (MODE == 5 && which == 2);
    if (MODE == 5) {
        if (which == 0)      { Cbase = args.C  + (size_t)bz * G_SIZE * DDIM; ldC = DDIM; }
        else if (which == 1) { Cbase = args.C2 + (size_t)bz * G_SIZE * DDIM; ldC = DDIM; }
        else                 { Cbase = args.C3 + (size_t)bz * DDIM * G_SIZE; ldC = G_SIZE; }
    } else if (MODE != 6) {
        Cbase = args.C + (size_t)bz * args.sC;
    }

    float bA[4], bB[4];
    int mkA[4], mkB[4];
    #pragma unroll
    for (int nt = 0; nt < 4; nt++) {
        const int n = nW + nt * 8 + lc;
        if (MODE == 6) { bA[nt] = args.bias[n]; bB[nt] = args.bias[n + 1]; }
        if (MODE == 3) { mkA[nt] = (n >= nkv); mkB[nt] = (n + 1 >= nkv); }
    }

    #pragma unroll
    for (int mt = 0; mt < 4; mt++) {
        const int mloc = wm * 64 + mt * 16 + lr;
        const int m = by * 128 + mloc;
        float inv0 = 1.f, inv8 = 1.f;
        if (MODE == 6) {
            const float* rs = args.rowsum + (size_t)bz * G_SIZE + by * 128;
            inv0 = 1.f / rs[mloc];
            inv8 = 1.f / rs[mloc + 8];
        }
        float p0 = 0.f, p8 = 0.f;

        #pragma unroll
        for (int nt = 0; nt < 4; nt++) {
            const int n = nW + nt * 8 + lc;
            const float* a = acc[mt][nt];

            if (MODE == 6) {
                float v0 = a[0] * inv0 + bA[nt], v1 = a[1] * inv0 + bB[nt];
                float v2 = a[2] * inv8 + bA[nt], v3 = a[3] * inv8 + bB[nt];
                float* base = args.Cf + (size_t)bz * args.sC;
                *(float2*)(base + (size_t)m * args.ldC + n)       = make_float2(v0, v1);
                *(float2*)(base + (size_t)(m + 8) * args.ldC + n) = make_float2(v2, v3);
                continue;
            }
            if (MODE == 3) {
                // alpha includes log2e: e = 2^(alpha*acc); masked -> -1e4 -> +0
                float x0 = mkA[nt] ? -1e4f : a[0] * alpha;
                float x1 = mkB[nt] ? -1e4f : a[1] * alpha;
                float x2 = mkA[nt] ? -1e4f : a[2] * alpha;
                float x3 = mkB[nt] ? -1e4f : a[3] * alpha;
                __half2 eA = ex2_h2(__floats2half2_rn(x0, x1));
                __half2 eB = ex2_h2(__floats2half2_rn(x2, x3));
                float2 fA = __half22float2(eA);
                float2 fB = __half22float2(eB);
                p0 += fA.x + fA.y;
                p8 += fB.x + fB.y;
                *(__half2*)(Cbase + (size_t)m * ldC + n)       = eA;
                *(__half2*)(Cbase + (size_t)(m + 8) * ldC + n) = eB;
                continue;
            }

            const float v0 = a[0], v1 = a[1], v2 = a[2], v3 = a[3];
            if (!trans) {
                __half2 hA = __floats2half2_rn(v0, v1);
                __half2 hB = __floats2half2_rn(v2, v3);
                *(__half2*)(Cbase + (size_t)m * ldC + n)       = hA;
                *(__half2*)(Cbase + (size_t)(m + 8) * ldC + n) = hB;
            } else {
                Cbase[(size_t)n * ldC + m] = __float2half_rn(v0);
                Cbase[(size_t)(n + 1) * ldC + m] = __float2half_rn(v1);
                Cbase[(size_t)n * ldC + m + 8] = __float2half_rn(v2);
                Cbase[(size_t)(n + 1) * ldC + m + 8] = __float2half_rn(v3);
            }
        }

        if (MODE == 3) {
            // reduce across the 4 lanes sharing each row, then direct global atomic
            p0 += __shfl_xor_sync(0xffffffffu, p0, 1);
            p0 += __shfl_xor_sync(0xffffffffu, p0, 2);
            p8 += __shfl_xor_sync(0xffffffffu, p8, 1);
            p8 += __shfl_xor_sync(0xffffffffu, p8, 2);
            if ((lane & 3) == 0) {
                float* rs = args.rowsum + (size_t)bz * G_SIZE + by * 128;
                atomicAdd(&rs[mloc], p0);
                atomicAdd(&rs[mloc + 8], p8);
            }
        }
    }
}

// ---------------------------------------------------------------------------
// Fused fp32 -> fp16 convert: data + 4 weights; also emits WvT (transposed Wv)
// ---------------------------------------------------------------------------
#define N_DATA4 (ROWS * DDIM / 4)
#define N_W4    (DDIM * DDIM / 4)
#define N_CVT4  (N_DATA4 + 4 * N_W4)

__global__ void __launch_bounds__(256)
cvt_all_kernel(const float4* __restrict__ data,
               const float4* __restrict__ wq, const float4* __restrict__ wk,
               const float4* __restrict__ wv, const float4* __restrict__ wo,
               f16* __restrict__ dataF,
               f16* __restrict__ wqF, f16* __restrict__ wkF,
               f16* __restrict__ wvF, f16* __restrict__ wvT,
               f16* __restrict__ woF)
{
    const int i = blockIdx.x * 256 + threadIdx.x;
    if (i >= N_CVT4) return;
    const float4* src;
    f16* dst;
    int off;
    int w = -1;
    if (i < N_DATA4) { src = data; dst = dataF; off = i; }
    else {
        const int jj = i - N_DATA4;
        w = jj / N_W4;
        off = jj - w * N_W4;
        src = (w == 0) ? wq : (w == 1) ? wk : (w == 2) ? wv : wo;
        dst = (w == 0) ? wqF : (w == 1) ? wkF : (w == 2) ? wvF : woF;
    }
    const float4 v = src[off];
    f16 h0 = __float2half_rn(v.x), h1 = __float2half_rn(v.y);
    f16 h2 = __float2half_rn(v.z), h3 = __float2half_rn(v.w);
    ((__half2*)dst)[off * 2]     = {h0, h1};
    ((__half2*)dst)[off * 2 + 1] = {h2, h3};
    if (w == 2) {
        // Wv is [v][in] row-major; also write WvT[in][v]
        const int row = (off * 4) >> 8;        // v index (DDIM=256 per row)
        const int col = (off * 4) & 255;       // in base
        wvT[(col + 0) * DDIM + row] = h0;
        wvT[(col + 1) * DDIM + row] = h1;
        wvT[(col + 2) * DDIM + row] = h2;
        wvT[(col + 3) * DDIM + row] = h3;
    }
}

// ---------------------------------------------------------------------------
// Fused: mask compaction + rowsum zero + key-row gather. One block per batch.
// ---------------------------------------------------------------------------
__global__ void __launch_bounds__(1024)
compact_gather_kernel(const int* __restrict__ mask, const f16* __restrict__ dataF,
                      int* __restrict__ kidx, int* __restrict__ nk,
                      float* __restrict__ rowsum, f16* __restrict__ dG)
{
    const int b = blockIdx.x;
    const int g = threadIdx.x;

    rowsum[b * G_SIZE + g] = 0.f;

    const int keep = (mask[b * G_SIZE + g] == 0);
    __shared__ int warpCnt[32];
    __shared__ int s_nk;
    const uint32_t bal = __ballot_sync(0xffffffffu, keep);
    const int lane = g & 31, w = g >> 5;
    const int pre = __popc(bal & ((1u << lane) - 1));
    if (lane == 0) warpCnt[w] = __popc(bal);
    __syncthreads();
    int base = 0;
    for (int i = 0; i < w; i++) base += warpCnt[i];
    if (keep) kidx[b * G_SIZE + base + pre] = g;
    if (g == 0) {
        int t = 0;
        for (int i = 0; i < 32; i++) t += warpCnt[i];
        nk[b] = t;
        s_nk = t;
    }
    __syncthreads();

    // Gather kept rows (512B each = 32 uint4), zero-pad to 128-row multiple
    const int n = s_nk;
    const int npad = (n + 127) & ~127;
    const int total = npad * 32;
    for (int idx = g; idx < total; idx += 1024) {
        const int jr = idx >> 5;
        const int c = idx & 31;
        uint4 v = make_uint4(0, 0, 0, 0);
        if (jr < n) {
            const size_t src = (size_t)(b * G_SIZE + kidx[b * G_SIZE + jr]) * DDIM;
            v = ((const uint4*)(dataF + src))[c];
        }
        ((uint4*)(dG + (size_t)(b * G_SIZE + jr) * DDIM))[c] = v;
    }
}

// ---------------------------------------------------------------------------
// Launch (6 kernels total)
// ---------------------------------------------------------------------------
extern "C" void kernel_launch(void* const* d_in, const int* in_sizes, int n_in,
                              void* d_out, int out_size)
{
    const float* data = (const float*)d_in[0];
    const int*   mask = (const int*)  d_in[1];
    const float* Wq   = (const float*)d_in[4];
    const float* Wk   = (const float*)d_in[5];
    const float* Wv   = (const float*)d_in[6];
    const float* Wo   = (const float*)d_in[7];
    const float* bo   = (const float*)d_in[8];
    float*       out  = (float*)d_out;

    f16 *dataF, *dG, *WqF, *WkF, *WvF, *WvT, *WoF, *Wvo, *Q, *K, *VWoT, *E;
    float* rowsum;
    int *kidx, *nk;
    cudaGetSymbolAddress((void**)&dataF, g_data);
    cudaGetSymbolAddress((void**)&dG, g_dG);
    cudaGetSymbolAddress((void**)&WqF, g_Wq);
    cudaGetSymbolAddress((void**)&WkF, g_Wk);
    cudaGetSymbolAddress((void**)&WvF, g_Wv);
    cudaGetSymbolAddress((void**)&WvT, g_WvT);
    cudaGetSymbolAddress((void**)&WoF, g_Wo);
    cudaGetSymbolAddress((void**)&Wvo, g_Wvo);
    cudaGetSymbolAddress((void**)&Q, g_Q);
    cudaGetSymbolAddress((void**)&K, g_K);
    cudaGetSymbolAddress((void**)&VWoT, g_VWoT);
    cudaGetSymbolAddress((void**)&E, g_E);
    cudaGetSymbolAddress((void**)&rowsum, g_rowsum);
    cudaGetSymbolAddress((void**)&kidx, g_kidx);
    cudaGetSymbolAddress((void**)&nk, g_nk);

    cudaFuncSetAttribute(gemm_mma<1>, cudaFuncAttributeMaxDynamicSharedMemorySize, SMEM_DYN);
    cudaFuncSetAttribute(gemm_mma<3>, cudaFuncAttributeMaxDynamicSharedMemorySize, SMEM_DYN);
    cudaFuncSetAttribute(gemm_mma<5>, cudaFuncAttributeMaxDynamicSharedMemorySize, SMEM_DYN);
    cudaFuncSetAttribute(gemm_mma<6>, cudaFuncAttributeMaxDynamicSharedMemorySize, SMEM_DYN);

    // 1) All fp32->fp16 conversions (+ WvT transpose)
    cvt_all_kernel<<<(N_CVT4 + 255) / 256, 256>>>(
        (const float4*)data, (const float4*)Wq, (const float4*)Wk,
        (const float4*)Wv, (const float4*)Wo,
        dataF, WqF, WkF, WvF, WvT, WoF);

    // 2) Wvo[n][in] = sum_v Wo[n][v] * Wv[v][in]  (NT: A=Wo, B=WvT)
    {
        GemmArgs a = {};
        a.A = WoF; a.B = WvT; a.C = Wvo;
        a.ldA = DDIM; a.ldB = DDIM; a.ldC = DDIM;
        a.sA = 0; a.sB = 0; a.sC = 0;
        a.nChunks = DDIM / 64;
        a.alpha = 1.f;
        dim3 grd(DDIM / 128, DDIM / 128, 1);
        gemm_mma<1><<<grd, 256, SMEM_DYN>>>(a);
    }

    // 3) Compaction + rowsum zero + gather
    compact_gather_kernel<<<BATCH, 1024>>>(mask, dataF, kidx, nk, rowsum, dG);

    GemmArgs ga = {};
    ga.rowsum = rowsum;
    ga.alpha = 1.f;

    // 4) Fused projections: Q (full), Kg (nk-limited), VWoT (nk-limited, trans)
    {
        dim3 grd(DDIM / 128, G_SIZE / 128, 3 * BATCH);
        GemmArgs a = ga;
        a.A = dataF; a.B = WqF; a.C = Q;
        a.A2 = dG; a.B2 = WkF; a.C2 = K; a.B3 = Wvo; a.C3 = VWoT;
        a.nkArr = nk;
        gemm_mma<5><<<grd, 256, SMEM_DYN>>>(a);
    }

    // 5) E[b][q][j] = 2^(NORM*log2e * Q_b @ Kg_b^T), j >= nk -> 0, + rowsum
    {
        dim3 grd(G_SIZE / 128, G_SIZE / 128, BATCH);
        GemmArgs a = ga;
        a.A = Q; a.B = K; a.nkArr = nk;
        a.ldA = DDIM; a.ldB = DDIM; a.ldC = G_SIZE;
        a.sA = (size_t)G_SIZE * DDIM; a.sB = (size_t)G_SIZE * DDIM;
        a.sC = (size_t)G_SIZE * G_SIZE;
        a.nChunks = DDIM / 64;
        a.alpha = NORM_F * LOG2E_F;
        a.C = E;
        gemm_mma<3><<<grd, 256, SMEM_DYN>>>(a);
    }

    // 6) out = (E_b @ VWoT_b^T) / rowsum + b_out   (fp32, K = ceil64(nk))
    {
        dim3 grd(DDIM / 128, G_SIZE / 128, BATCH);
        GemmArgs a = ga;
        a.A = E; a.B = VWoT; a.nkArr = nk;
        a.ldA = G_SIZE; a.ldB = G_SIZE; a.ldC = DDIM;
        a.sA = (size_t)G_SIZE * G_SIZE; a.sB = (size_t)DDIM * G_SIZE;
        a.sC = (size_t)G_SIZE * DDIM;
        a.nChunks = G_SIZE / 64;    // overridden per-batch in kernel
        a.Cf = out; a.bias = bo;
        gemm_mma<6><<<grd, 256, SMEM_DYN>>>(a);
    }
}